// round 1
// baseline (speedup 1.0000x reference)
#include <cuda_runtime.h>

// Problem: x (N=128, C=128, H=56, W=56) f32; w (O=32, K=3, C=128) f32
// y[n,j,h,w] = sum_{k,i} s[n,i,h, w+k] * w[j,k,i]
//   where s[u] = 0 for u==0 or u==57 (SAME padding after the W-roll),
//         s[1] = x[...,55] (wrap from roll), s[t] = x[..., t-2] for t=2..56
// out[n,j,(h+1)%56,w] = y[n,j,h,w]   (H-roll folded into the store)

typedef unsigned long long u64;

__device__ __forceinline__ u64 pack_dup(float v) {
    u64 r; asm("mov.b64 %0, {%1, %1};" : "=l"(r) : "f"(v)); return r;
}
__device__ __forceinline__ u64 ffma2(u64 a, u64 b, u64 c) {
    u64 d; asm("fma.rn.f32x2 %0, %1, %2, %3;" : "=l"(d) : "l"(a), "l"(b), "l"(c)); return d;
}
__device__ __forceinline__ void unpack2(u64 v, float &lo, float &hi) {
    asm("mov.b64 {%0, %1}, %2;" : "=f"(lo), "=f"(hi) : "l"(v));
}

// Block = (n, 4 h-rows). 224 threads: th (4 h) x jg (8 groups of 4 j) x wg (7 groups of 8 w).
// Smem: ws[128 c][3 k][32 j] = 48KB  +  xs[32 c][4 h][60] = 30KB   -> 79,872 B dynamic.
#define THREADS 224
#define SMEM_FLOATS (12288 + 32 * 4 * 60)

__global__ __launch_bounds__(THREADS, 2)
void shiftconv_kernel(const float* __restrict__ x,
                      const float* __restrict__ wsrc,
                      float* __restrict__ out) {
    extern __shared__ float smem[];
    float* ws = smem;            // [c*96 + k*32 + j]
    float* xs = smem + 12288;    // [c*240 + h*60 + t]

    const int tid = threadIdx.x;
    const int th  = tid / 56;        // 0..3
    const int r   = tid % 56;
    const int jg  = r / 7;           // 0..7
    const int wg  = r % 7;           // 0..6
    const int j0  = jg * 4;
    const int w0  = wg * 8;
    const int hb  = blockIdx.x;      // 0..13
    const int n   = blockIdx.y;      // 0..127
    const int h   = hb * 4 + th;     // 0..55

    // Load all weights once: coalesced global read, transposed smem write.
    for (int idx = tid; idx < 32 * 3 * 128; idx += THREADS) {
        int j = idx / 384;
        int rem = idx % 384;
        int k = rem / 128;
        int c = rem % 128;
        ws[c * 96 + k * 32 + j] = wsrc[idx];
    }
    // Zero the pad slots (t=0 and t=57) of every xs row; chunk loads never touch them.
    for (int idx = tid; idx < 32 * 4; idx += THREADS) {
        int c = idx / 4, hh = idx % 4;
        xs[c * 240 + hh * 60 + 0]  = 0.f;
        xs[c * 240 + hh * 60 + 57] = 0.f;
    }

    u64 acc[2][8];
    #pragma unroll
    for (int p = 0; p < 2; p++)
        #pragma unroll
        for (int q = 0; q < 8; q++) acc[p][q] = 0ull;   // (0.f, 0.f)

    for (int c0 = 0; c0 < 128; c0 += 32) {
        __syncthreads();   // previous chunk's compute done (first iter: init visible)
        // Stage 32 channels x 4 h-rows, with roll+pad folded into slot index.
        for (int idx = tid; idx < 32 * 4 * 56; idx += THREADS) {
            int c   = idx / 224;
            int rem = idx % 224;
            int hh  = rem / 56;
            int w   = rem % 56;
            float v = x[((size_t)n * 128 + c0 + c) * 3136 + (hb * 4 + hh) * 56 + w];
            int t = (w == 55) ? 1 : (w + 2);
            xs[c * 240 + hh * 60 + t] = v;
        }
        __syncthreads();

        const float* xr = xs + th * 60 + w0;
        const float* wr = ws + c0 * 96 + j0;
        for (int cc = 0; cc < 32; cc++) {
            // 10 staged x values (s[w0] .. s[w0+9]) as aligned 8B pairs, then dup-pack.
            float xv[10];
            const float2* xp = (const float2*)(xr + cc * 240);
            #pragma unroll
            for (int t = 0; t < 5; t++) {
                float2 p = xp[t];
                xv[2 * t] = p.x; xv[2 * t + 1] = p.y;
            }
            u64 xd[10];
            #pragma unroll
            for (int s = 0; s < 10; s++) xd[s] = pack_dup(xv[s]);

            // Weight j-pairs straight from smem as 8B loads: (j0+2p, j0+2p+1) for k=0..2.
            const u64* wq = (const u64*)(wr + cc * 96);
            u64 wp[2][3];
            #pragma unroll
            for (int k = 0; k < 3; k++) {
                wp[0][k] = wq[k * 16];
                wp[1][k] = wq[k * 16 + 1];
            }

            #pragma unroll
            for (int p = 0; p < 2; p++)
                #pragma unroll
                for (int ww = 0; ww < 8; ww++) {
                    acc[p][ww] = ffma2(wp[p][0], xd[ww],     acc[p][ww]);
                    acc[p][ww] = ffma2(wp[p][1], xd[ww + 1], acc[p][ww]);
                    acc[p][ww] = ffma2(wp[p][2], xd[ww + 2], acc[p][ww]);
                }
        }
    }

    // Store with the H-roll folded in: y[...,h,...] -> out[...,(h+1)%56,...]
    const int ho = (h + 1) % 56;
    #pragma unroll
    for (int p = 0; p < 2; p++) {
        float lo[8], hi[8];
        #pragma unroll
        for (int ww = 0; ww < 8; ww++) unpack2(acc[p][ww], lo[ww], hi[ww]);
        int ja = j0 + 2 * p;
        int jb = ja + 1;
        float4* oa = (float4*)(out + (((size_t)n * 32 + ja) * 56 + ho) * 56 + w0);
        float4* ob = (float4*)(out + (((size_t)n * 32 + jb) * 56 + ho) * 56 + w0);
        oa[0] = make_float4(lo[0], lo[1], lo[2], lo[3]);
        oa[1] = make_float4(lo[4], lo[5], lo[6], lo[7]);
        ob[0] = make_float4(hi[0], hi[1], hi[2], hi[3]);
        ob[1] = make_float4(hi[4], hi[5], hi[6], hi[7]);
    }
}

extern "C" void kernel_launch(void* const* d_in, const int* in_sizes, int n_in,
                              void* d_out, int out_size) {
    const float* x = (const float*)d_in[0];   // (128,128,56,56)
    const float* w = (const float*)d_in[1];   // (32,3,128)
    float* out = (float*)d_out;               // (128,32,56,56)

    const int smem_bytes = SMEM_FLOATS * (int)sizeof(float);   // 79,872 B
    cudaFuncSetAttribute(shiftconv_kernel,
                         cudaFuncAttributeMaxDynamicSharedMemorySize, smem_bytes);

    dim3 grid(14, 128);
    shiftconv_kernel<<<grid, THREADS, smem_bytes>>>(x, w, out);
}

// round 2
// speedup vs baseline: 1.0096x; 1.0096x over previous
#include <cuda_runtime.h>

// Problem: x (N=128, C=128, H=56, W=56) f32; w (O=32, K=3, C=128) f32
// y[n,j,h,w] = sum_{k,i} s[n,i,h, w+k] * w[j,k,i]
//   where s[u] = 0 for u==0 or u==57 (SAME padding after the W-roll),
//         s[1] = x[...,55] (wrap from roll), s[t] = x[..., t-2] for t=2..56
// out[n,j,(h+1)%56,w] = y[n,j,h,w]   (H-roll folded into the store)

typedef unsigned long long u64;

__device__ __forceinline__ u64 pack_dup(float v) {
    u64 r; asm("mov.b64 %0, {%1, %1};" : "=l"(r) : "f"(v)); return r;
}
__device__ __forceinline__ u64 ffma2(u64 a, u64 b, u64 c) {
    u64 d; asm("fma.rn.f32x2 %0, %1, %2, %3;" : "=l"(d) : "l"(a), "l"(b), "l"(c)); return d;
}
__device__ __forceinline__ void unpack2(u64 v, float &lo, float &hi) {
    asm("mov.b64 {%0, %1}, %2;" : "=f"(lo), "=f"(hi) : "l"(v));
}

// Block = (n, 4 h-rows). 224 threads: th (4 h) x jg (8 groups of 4 j) x wg (7 groups of 8 w).
// Smem: ws[128 c][3 k][32 j] = 48KB  +  xs[32 c][4 h][60] = 30KB   -> 79,872 B dynamic.
#define THREADS 224
#define SMEM_FLOATS (12288 + 32 * 4 * 60)

__global__ __launch_bounds__(THREADS, 2)
void shiftconv_kernel(const float* __restrict__ x,
                      const float* __restrict__ wsrc,
                      float* __restrict__ out) {
    extern __shared__ float smem[];
    float* ws = smem;            // [c*96 + k*32 + j]
    float* xs = smem + 12288;    // [c*240 + h*60 + t]

    const int tid = threadIdx.x;
    const int th  = tid / 56;        // 0..3
    const int r   = tid % 56;
    const int jg  = r / 7;           // 0..7
    const int wg  = r % 7;           // 0..6
    const int j0  = jg * 4;
    const int w0  = wg * 8;
    const int hb  = blockIdx.x;      // 0..13
    const int n   = blockIdx.y;      // 0..127
    const int h   = hb * 4 + th;     // 0..55

    // Load all weights once: coalesced global read, transposed smem write.
    for (int idx = tid; idx < 32 * 3 * 128; idx += THREADS) {
        int j = idx / 384;
        int rem = idx % 384;
        int k = rem / 128;
        int c = rem % 128;
        ws[c * 96 + k * 32 + j] = wsrc[idx];
    }
    // Zero the pad slots (t=0 and t=57) of every xs row; chunk loads never touch them.
    for (int idx = tid; idx < 32 * 4; idx += THREADS) {
        int c = idx / 4, hh = idx % 4;
        xs[c * 240 + hh * 60 + 0]  = 0.f;
        xs[c * 240 + hh * 60 + 57] = 0.f;
    }

    u64 acc[2][8];
    #pragma unroll
    for (int p = 0; p < 2; p++)
        #pragma unroll
        for (int q = 0; q < 8; q++) acc[p][q] = 0ull;   // (0.f, 0.f)

    for (int c0 = 0; c0 < 128; c0 += 32) {
        __syncthreads();   // previous chunk's compute done (first iter: init visible)
        // Stage 32 channels x 4 h-rows, with roll+pad folded into slot index.
        for (int idx = tid; idx < 32 * 4 * 56; idx += THREADS) {
            int c   = idx / 224;
            int rem = idx % 224;
            int hh  = rem / 56;
            int w   = rem % 56;
            float v = x[((size_t)n * 128 + c0 + c) * 3136 + (hb * 4 + hh) * 56 + w];
            int t = (w == 55) ? 1 : (w + 2);
            xs[c * 240 + hh * 60 + t] = v;
        }
        __syncthreads();

        const float* xr = xs + th * 60 + w0;
        const float* wr = ws + c0 * 96 + j0;
        for (int cc = 0; cc < 32; cc++) {
            // 10 staged x values (s[w0] .. s[w0+9]) as aligned 8B pairs, then dup-pack.
            float xv[10];
            const float2* xp = (const float2*)(xr + cc * 240);
            #pragma unroll
            for (int t = 0; t < 5; t++) {
                float2 p = xp[t];
                xv[2 * t] = p.x; xv[2 * t + 1] = p.y;
            }
            u64 xd[10];
            #pragma unroll
            for (int s = 0; s < 10; s++) xd[s] = pack_dup(xv[s]);

            // Weight j-pairs straight from smem as 8B loads: (j0+2p, j0+2p+1) for k=0..2.
            const u64* wq = (const u64*)(wr + cc * 96);
            u64 wp[2][3];
            #pragma unroll
            for (int k = 0; k < 3; k++) {
                wp[0][k] = wq[k * 16];
                wp[1][k] = wq[k * 16 + 1];
            }

            #pragma unroll
            for (int p = 0; p < 2; p++)
                #pragma unroll
                for (int ww = 0; ww < 8; ww++) {
                    acc[p][ww] = ffma2(wp[p][0], xd[ww],     acc[p][ww]);
                    acc[p][ww] = ffma2(wp[p][1], xd[ww + 1], acc[p][ww]);
                    acc[p][ww] = ffma2(wp[p][2], xd[ww + 2], acc[p][ww]);
                }
        }
    }

    // Store with the H-roll folded in: y[...,h,...] -> out[...,(h+1)%56,...]
    const int ho = (h + 1) % 56;
    #pragma unroll
    for (int p = 0; p < 2; p++) {
        float lo[8], hi[8];
        #pragma unroll
        for (int ww = 0; ww < 8; ww++) unpack2(acc[p][ww], lo[ww], hi[ww]);
        int ja = j0 + 2 * p;
        int jb = ja + 1;
        float4* oa = (float4*)(out + (((size_t)n * 32 + ja) * 56 + ho) * 56 + w0);
        float4* ob = (float4*)(out + (((size_t)n * 32 + jb) * 56 + ho) * 56 + w0);
        oa[0] = make_float4(lo[0], lo[1], lo[2], lo[3]);
        oa[1] = make_float4(lo[4], lo[5], lo[6], lo[7]);
        ob[0] = make_float4(hi[0], hi[1], hi[2], hi[3]);
        ob[1] = make_float4(hi[4], hi[5], hi[6], hi[7]);
    }
}

extern "C" void kernel_launch(void* const* d_in, const int* in_sizes, int n_in,
                              void* d_out, int out_size) {
    const float* x = (const float*)d_in[0];   // (128,128,56,56)
    const float* w = (const float*)d_in[1];   // (32,3,128)
    float* out = (float*)d_out;               // (128,32,56,56)

    const int smem_bytes = SMEM_FLOATS * (int)sizeof(float);   // 79,872 B
    cudaFuncSetAttribute(shiftconv_kernel,
                         cudaFuncAttributeMaxDynamicSharedMemorySize, smem_bytes);

    dim3 grid(14, 128);
    shiftconv_kernel<<<grid, THREADS, smem_bytes>>>(x, w, out);
}

// round 4
// speedup vs baseline: 1.5823x; 1.5673x over previous
#include <cuda_runtime.h>
#include <cstdint>

// y[n,j,h,w] = sum_{k,c} s[w+k][c] * wgt[j,k,c];  out[n,j,(h+1)%56,w] = y
//   s[u][c]: u==0||u==57 -> 0 ; u==1 -> x[...,55] (W-roll wrap) ; else x[...,u-2]
// Per tile (n, h-pair): D[128 m, 32 j] = A[128, 384] * B[32, 384]^T via mma.sync
// bf16 hi/lo split, 3 passes: AhBh + AlBh + AhBl (residual ~2^-17).

#define NT      3584
#define NCTA    148
#define THREADS 256

// smem byte offsets
#define SM_WHI 0u          // weights hi: [j][384 k] bf16, 768B rows, seg-swizzled
#define SM_WLO 24576u
#define SM_THI 49152u      // A hi: [hs][64 u][128 c] bf16, 256B rows, seg-swizzled
#define SM_TLO 81920u
#define SM_S   114688u     // f32 staged: [hs][128 c][64 w-words], pair-swizzled
#define SM_TOTAL 180224

static __device__ __forceinline__ uint32_t s2u(const void* p) {
    uint32_t a;
    asm("{ .reg .u64 t; cvta.to.shared.u64 t, %1; cvt.u32.u64 %0, t; }" : "=r"(a) : "l"(p));
    return a;
}
// packed bf16x2: low half <- lo, high half <- hi
static __device__ __forceinline__ uint32_t bf2(float lo, float hi) {
    uint32_t r;
    asm("cvt.rn.bf16x2.f32 %0, %1, %2;" : "=r"(r) : "f"(hi), "f"(lo));
    return r;
}
static __device__ __forceinline__ void ldsm4(uint32_t* r, uint32_t addr) {
    asm volatile("ldmatrix.sync.aligned.m8n8.x4.shared.b16 {%0,%1,%2,%3}, [%4];"
                 : "=r"(r[0]), "=r"(r[1]), "=r"(r[2]), "=r"(r[3]) : "r"(addr));
}
static __device__ __forceinline__ void mma16816(float* c, const uint32_t* a, const uint32_t* b) {
    asm volatile("mma.sync.aligned.m16n8k16.row.col.f32.bf16.bf16.f32 "
                 "{%0,%1,%2,%3}, {%4,%5,%6,%7}, {%8,%9}, {%0,%1,%2,%3};"
                 : "+f"(c[0]), "+f"(c[1]), "+f"(c[2]), "+f"(c[3])
                 : "r"(a[0]), "r"(a[1]), "r"(a[2]), "r"(a[3]), "r"(b[0]), "r"(b[1]));
}

// stage one tile's x slice into S (f32, swizzled) via cp.async (no regs)
static __device__ __forceinline__ void stage_cp(const float* __restrict__ x,
                                                uint32_t sS, int n, int hp, int tid) {
    const float* base = x + (size_t)n * 128 * 3136 + hp * 2 * 56;
    #pragma unroll
    for (int it = 0; it < 28; it++) {
        int idx = it * 256 + tid;          // 0..7167 = 2 hs * 128 c * 28 w-pairs
        int w2  = idx % 28;
        int c   = (idx / 28) & 127;
        int hs  = idx / 3584;
        const float* src = base + (size_t)c * 3136 + hs * 56 + w2 * 2;
        uint32_t key = (uint32_t)((c >> 1) & 15);
        uint32_t dst = sS + (uint32_t)hs * 32768 + (uint32_t)c * 256
                          + ((((uint32_t)w2) ^ key) << 3);
        asm volatile("cp.async.ca.shared.global [%0], [%1], 8;" :: "r"(dst), "l"(src));
    }
    asm volatile("cp.async.commit_group;" ::: "memory");
}

__global__ __launch_bounds__(THREADS, 1)
void shiftconv_mma(const float* __restrict__ x,
                   const float* __restrict__ wsrc,
                   float* __restrict__ out) {
    extern __shared__ char smem[];
    const uint32_t sb = s2u(smem);
    const int tid  = threadIdx.x;
    const int lane = tid & 31;
    const int wid  = tid >> 5;

    // ---- one-time init: weights hi/lo (swizzled) + zero pad rows of T ----
    for (int i = tid; i < 6144; i += THREADS) {
        int j = i / 192, kp = i % 192, k = kp * 2;
        float2 ab = *(const float2*)(wsrc + j * 384 + k);
        uint32_t hi = bf2(ab.x, ab.y);
        float ea = __uint_as_float(hi << 16);
        float eb = __uint_as_float(hi & 0xffff0000u);
        uint32_t lo = bf2(ab.x - ea, ab.y - eb);
        uint32_t seg = ((uint32_t)(k >> 3)) ^ (uint32_t)(j & 7);
        uint32_t off = (uint32_t)j * 768 + (seg << 4) + ((k & 7) << 1);
        *(uint32_t*)(smem + SM_WHI + off) = hi;
        *(uint32_t*)(smem + SM_WLO + off) = lo;
    }
    // zero T rows u in {0, 57..63} for both slabs, both hs (never rewritten)
    for (int i = tid; i < 2048; i += THREADS) {
        int slab = i >> 10;
        int rem  = i & 1023;
        int hs   = rem >> 9;
        int rw   = (rem >> 6) & 7;
        int u    = (rw == 0) ? 0 : (56 + rw);
        int wd   = i & 63;
        *(uint32_t*)(smem + (slab ? SM_TLO : SM_THI)
                     + (uint32_t)hs * 16384 + (uint32_t)u * 256 + (uint32_t)wd * 4) = 0u;
    }
    __syncthreads();

    // ---- per-warp mma constants ----
    const int hsub  = wid >> 2;
    const int wpos0 = (wid & 3) * 16;
    const int g  = lane >> 2, tg = lane & 3;
    const int al = lane & 15;                     // A frag: row index within 16
    const uint32_t ad = (uint32_t)(lane >> 4);    // A frag: +1 k-seg for lanes 16-31
    const int bj = (lane & 7) + ((lane >> 4) << 3);   // B frag x4 j-row
    const uint32_t bd = (uint32_t)((lane >> 3) & 1);  // B frag: +1 k-seg
    // A row bases per tap (clamp junk rows)
    uint32_t abase[3], amask[3];
    #pragma unroll
    for (int tp = 0; tp < 3; tp++) {
        int u = wpos0 + al + tp; if (u > 63) u = 63;
        abase[tp] = (uint32_t)hsub * 16384 + (uint32_t)u * 256;
        amask[tp] = (uint32_t)(u & 7);
    }
    const uint32_t bj7  = (uint32_t)(bj & 7);
    const uint32_t brow0 = (uint32_t)bj * 768;
    const uint32_t brow1 = (uint32_t)(bj + 16) * 768;
    const uint32_t bj71 = (uint32_t)((bj + 16) & 7);

    int t0 = blockIdx.x;
    stage_cp(x, sb + SM_S, t0 / 28, t0 % 28, tid);

    for (int t = t0; t < NT; t += NCTA) {
        const int n = t / 28, hp = t % 28;

        asm volatile("cp.async.wait_group 0;" ::: "memory");
        __syncthreads();

        // ---- transpose + bf16 hi/lo split:  S [c][w] f32  ->  T [u][c] bf16 ----
        #pragma unroll 2
        for (int s = 0; s < 14; s++) {
            int slot = wid * 14 + s;              // 0..111 = 2 hs * 56 u
            int hs = slot >= 56;
            int uu = (slot - hs * 56) + 1;        // 1..56
            int w  = (uu == 1) ? 55 : (uu - 2);
            uint32_t w2 = (uint32_t)(w >> 1), wb = (uint32_t)(w & 1);
            #pragma unroll
            for (int q = 0; q < 2; q++) {
                int cp = lane + 32 * q;           // c-pair 0..63
                int c  = cp * 2;
                uint32_t key = (uint32_t)(cp & 15);
                const char* ra = smem + SM_S + (uint32_t)hs * 32768 + (uint32_t)c * 256
                                 + (((w2 ^ key) * 2 + wb) << 2);
                float va = *(const float*)ra;
                float vb = *(const float*)(ra + 256);
                uint32_t hi = bf2(va, vb);
                float ea = __uint_as_float(hi << 16);
                float eb = __uint_as_float(hi & 0xffff0000u);
                uint32_t lo = bf2(va - ea, vb - eb);
                uint32_t seg = ((uint32_t)(c >> 3)) ^ (uint32_t)(uu & 7);
                uint32_t off = (uint32_t)hs * 16384 + (uint32_t)uu * 256
                               + (seg << 4) + ((uint32_t)(c & 7) << 1);
                *(uint32_t*)(smem + SM_THI + off) = hi;
                *(uint32_t*)(smem + SM_TLO + off) = lo;
            }
        }
        __syncthreads();

        // ---- prefetch next tile while MMA runs ----
        if (t + NCTA < NT)
            stage_cp(x, sb + SM_S, (t + NCTA) / 28, (t + NCTA) % 28, tid);

        // ---- MMA: 24 k-steps x (6 ldmatrix.x4 + 12 mma) ----
        float acc[4][4];
        #pragma unroll
        for (int i = 0; i < 4; i++)
            #pragma unroll
            for (int q = 0; q < 4; q++) acc[i][q] = 0.f;

        #pragma unroll
        for (int tp = 0; tp < 3; tp++) {
            #pragma unroll
            for (int cb = 0; cb < 8; cb++) {
                const uint32_t cs = (uint32_t)(cb * 2);
                const uint32_t aoff = abase[tp] + (((cs + ad) ^ amask[tp]) << 4);
                uint32_t ah[4], alr[4], bh[8], bl[8];
                ldsm4(ah,  sb + SM_THI + aoff);
                ldsm4(alr, sb + SM_TLO + aoff);
                const uint32_t bsg = (uint32_t)(tp * 16) + cs + bd;
                const uint32_t bo0 = brow0 + ((bsg ^ bj7)  << 4);
                const uint32_t bo1 = brow1 + ((bsg ^ bj71) << 4);
                ldsm4(bh,     sb + SM_WHI + bo0);
                ldsm4(bh + 4, sb + SM_WHI + bo1);
                ldsm4(bl,     sb + SM_WLO + bo0);
                ldsm4(bl + 4, sb + SM_WLO + bo1);
                #pragma unroll
                for (int nt = 0; nt < 4; nt++) {
                    mma16816(acc[nt], ah,  bh + nt * 2);
                    mma16816(acc[nt], alr, bh + nt * 2);
                    mma16816(acc[nt], ah,  bl + nt * 2);
                }
            }
        }

        // ---- store D with H-roll folded ----
        {
            const int h  = hp * 2 + hsub;
            const int ho = (h + 1) % 56;
            float* ob = out + (size_t)n * 100352 + ho * 56;
            #pragma unroll
            for (int rr = 0; rr < 2; rr++) {
                const int wpos = wpos0 + g + rr * 8;
                if (wpos < 56) {
                    #pragma unroll
                    for (int nt = 0; nt < 4; nt++) {
                        const int j = nt * 8 + tg * 2;
                        ob[(size_t)j * 3136 + wpos]       = acc[nt][rr * 2 + 0];
                        ob[(size_t)(j + 1) * 3136 + wpos] = acc[nt][rr * 2 + 1];
                    }
                }
            }
        }
        // next loop iteration's wait_group+syncthreads protects S and T reuse
    }
}

extern "C" void kernel_launch(void* const* d_in, const int* in_sizes, int n_in,
                              void* d_out, int out_size) {
    const float* x = (const float*)d_in[0];   // (128,128,56,56)
    const float* w = (const float*)d_in[1];   // (32,3,128)
    float* out = (float*)d_out;               // (128,32,56,56)

    cudaFuncSetAttribute(shiftconv_mma, cudaFuncAttributeMaxDynamicSharedMemorySize, SM_TOTAL);
    shiftconv_mma<<<NCTA, THREADS, SM_TOTAL>>>(x, w, out);
}